// round 15
// baseline (speedup 1.0000x reference)
#include <cuda_runtime.h>
#include <cuda_fp16.h>
#include <cstdint>

#define BATCH 32768
#define IDIM  128
#define HDIM  256
#define ADIM  32
#define MT    32
#define NT    256
#define NBLK  (BATCH/MT)

// ---- packed fp16 scratch (uint32 units) ----
#define XPK   0u
#define H0PK  2097152u
#define H1PK  6291456u
#define W0X   10485760u
#define W0H   10534912u
#define W1X   10633216u
#define W1H   10731520u
#define SCR_TOTAL 10829824u
__device__ uint32_t scr[SCR_TOTAL];

// uint4 base indices
#define XPK4  (XPK/4)
#define H0PK4 (H0PK/4)
#define H1PK4 (H1PK/4)
#define W0X4  (W0X/4)
#define W0H4  (W0H/4)
#define W1X4  (W1X/4)
#define W1H4  (W1H/4)

static __device__ __forceinline__ uint32_t h2p(float a, float b) {
    __half2 h = __floats2half2_rn(a, b);
    return *reinterpret_cast<uint32_t*>(&h);
}
static __device__ __forceinline__ uint4 ldg_cg4(const uint4* p) {
    uint4 v;
    asm volatile("ld.global.cg.v4.u32 {%0,%1,%2,%3}, [%4];"
        : "=r"(v.x), "=r"(v.y), "=r"(v.z), "=r"(v.w) : "l"(p));
    return v;
}
static __device__ __forceinline__ void mma16(float c[4], const uint32_t a[4],
                                             const uint32_t b[2]) {
    asm volatile(
        "mma.sync.aligned.m16n8k16.row.col.f32.f16.f16.f32 "
        "{%0,%1,%2,%3},{%4,%5,%6,%7},{%8,%9},{%0,%1,%2,%3};"
        : "+f"(c[0]), "+f"(c[1]), "+f"(c[2]), "+f"(c[3])
        : "r"(a[0]), "r"(a[1]), "r"(a[2]), "r"(a[3]), "r"(b[0]), "r"(b[1]));
}
static __device__ __forceinline__ float sigf(float x) {
    return __fdividef(1.0f, 1.0f + __expf(-x));
}
static __device__ __forceinline__ float tanhff(float x) {
    float ax = fabsf(x), e = __expf(-2.0f * ax);
    return copysignf(__fdividef(1.0f - e, 1.0f + e), x);
}
static __device__ __forceinline__ float gru1(float rp, float zp, float ip,
                                             float hp, float hv) {
    float r = sigf(rp), z = sigf(zp);
    float n = tanhff(ip + r * hp);
    return n + z * (hv - n);
}

// ---------- merged pre-kernel: pack weights + A-sources ----------
__global__ void __launch_bounds__(256)
pack_all(const float* __restrict__ x,    const float* __restrict__ hin,
         const float* __restrict__ wih0, const float* __restrict__ whh0,
         const float* __restrict__ wih1, const float* __restrict__ whh1)
{
    int tid = threadIdx.x;
    if (blockIdx.x < 336) {
        int i = blockIdx.x * 256 + tid;
        if (i >= 86016) return;
        const float* src; uint32_t base4; int K; int l = i;
        if (l < 12288)                 { src = wih0; base4 = W0X4; K = 128; }
        else if ((l -= 12288) < 24576) { src = whh0; base4 = W0H4; K = 256; }
        else if ((l -= 24576) < 24576) { src = wih1; base4 = W1X4; K = 256; }
        else { l -= 24576;               src = whh1; base4 = W1H4; K = 256; }
        const int KB = K >> 4;
        int lane = l & 31, blk = l >> 5;
        int j = blk % KB, pair = (blk / KB) & 15, g = blk / (KB * 16);
        int gid = lane >> 2, tig = lane & 3;
        int n_e = g * 256 + pair * 16 + gid;
        int k0  = 16 * j + 2 * tig;
        const float* pe = src + (size_t)n_e * K + k0;
        const float* po = src + (size_t)(n_e + 8) * K + k0;
        uint4 v;
        v.x = h2p(pe[0], pe[1]); v.y = h2p(pe[8], pe[9]);
        v.z = h2p(po[0], po[1]); v.w = h2p(po[8], po[9]);
        ((uint4*)(scr + 0))[base4 + (uint32_t)l] = v;
    } else {
        int bb2 = blockIdx.x - 336;
        int bb = bb2 & 255, m = bb2 >> 8;
        const float* src; uint32_t base4; int K;
        if (m == 0)      { src = x;   base4 = XPK4;  K = IDIM; }
        else if (m == 1) { src = hin; base4 = H0PK4; K = HDIM; }
        else             { src = hin + (size_t)BATCH * HDIM; base4 = H1PK4; K = HDIM; }
        src += (size_t)bb * 128 * K;
        const int KB = K >> 4;
        const int nout = 8 * KB * 32;
        uint4* outp = (uint4*)(scr + 0) + base4 + (size_t)bb * nout;
        for (int o = tid; o < nout; o += 256) {
            int lane = o & 31, j = (o >> 5) % KB, mb = (o >> 5) / KB;
            int gid = lane >> 2, tig = lane & 3;
            int r0 = mb * 16 + gid, k0 = 16 * j + 2 * tig;
            const float* p0 = src + (size_t)r0 * K + k0;
            const float* p1 = src + (size_t)(r0 + 8) * K + k0;
            uint4 v;
            v.x = h2p(p0[0], p0[1]); v.y = h2p(p1[0], p1[1]);
            v.z = h2p(p0[8], p0[9]); v.w = h2p(p1[8], p1[9]);
            outp[o] = v;
        }
    }
}

#define H0ST 132   // u32 stride per row: 128 data (256 fp16) + 4 pad
#define SMEM_H0 (MT * H0ST * 4)   // 16896 B per CTA (dynamic)

__global__ void __launch_bounds__(NT, 3)
gru_ac_kernel(const float* __restrict__ x,    const float* __restrict__ hin,
              const float* __restrict__ bih0, const float* __restrict__ bhh0,
              const float* __restrict__ bih1, const float* __restrict__ bhh1,
              const float* __restrict__ wp,   const float* __restrict__ bp,
              const float* __restrict__ wv,   const float* __restrict__ bv,
              float* __restrict__ out)
{
    extern __shared__ uint32_t h0s[];           // MT x H0ST fp16x2 h0 copy
    const uint4* S4 = (const uint4*)(scr + 0);
    const int tid  = threadIdx.x;
    const int lane = tid & 31;
    const int wid  = tid >> 5;
    const int wm   = wid >> 2;     // 0..1 : 16-row band
    const int wn   = wid & 3;      // 0..3 : 16-col band
    const int gID  = lane >> 2;
    const int tig  = lane & 3;
    const int bb   = blockIdx.x;
    const int rowbase = bb * MT;
    const int gm   = bb * 2 + wm;  // global m16-tile index

    float* outL  = out;
    float* outV  = out + (size_t)BATCH * ADIM;
    float* hbase = out + (size_t)BATCH * (ADIM + 1);   // [2][B][H]

    for (int layer = 0; layer < 2; ++layer) {
        const float* bih = layer ? bih1 : bih0;
        const float* bhh = layer ? bhh1 : bhh0;
        const float* asrch = hin + (size_t)layer * BATCH * HDIM
                                 + (size_t)rowbase * HDIM;
        float* hdst = hbase + (size_t)layer * BATCH * HDIM
                            + (size_t)rowbase * HDIM;

        for (int q = 0; q < 4; ++q) {
            float aR[2][4], aZ[2][4], aI[2][4], aH[2][4];
            #pragma unroll
            for (int s = 0; s < 2; ++s)
                #pragma unroll
                for (int k = 0; k < 4; ++k) {
                    aR[s][k] = 0.f; aZ[s][k] = 0.f;
                    aI[s][k] = 0.f; aH[s][k] = 0.f;
                }
            const int wpair = q * 4 + wn;

            auto mmastep = [&](const uint32_t af[4], const uint4 wv[3],
                               float (*accN)[4]) {
                #pragma unroll
                for (int s = 0; s < 2; ++s) {
                    uint32_t bR[2], bZ[2], bN[2];
                    bR[0] = s ? wv[0].z : wv[0].x;
                    bR[1] = s ? wv[0].w : wv[0].y;
                    bZ[0] = s ? wv[1].z : wv[1].x;
                    bZ[1] = s ? wv[1].w : wv[1].y;
                    bN[0] = s ? wv[2].z : wv[2].x;
                    bN[1] = s ? wv[2].w : wv[2].y;
                    mma16(aR[s], af, bR);
                    mma16(aZ[s], af, bZ);
                    mma16(accN[s], af, bN);
                }
            };

            auto phase_pk = [&](uint32_t a_base4, uint32_t w_base4, int KB,
                                float (*accN)[4]) {
                uint32_t ia = a_base4 + (uint32_t)(gm * KB) * 32 + lane;
                uint32_t iw[3];
                #pragma unroll
                for (int g = 0; g < 3; ++g)
                    iw[g] = w_base4 + (uint32_t)((g * 16 + wpair) * KB) * 32 + lane;
                for (int j = 0; j < KB; ++j) {
                    uint4 a0 = S4[ia + j * 32];            // A: L1-cached
                    uint4 wv[3];
                    #pragma unroll
                    for (int g = 0; g < 3; ++g)
                        wv[g] = ldg_cg4(&S4[iw[g] + j * 32]);  // W: L2-only
                    uint32_t af[4] = {a0.x, a0.y, a0.z, a0.w};
                    mmastep(af, wv, accN);
                }
            };

            // smem-A phase (layer 1 x-part: A = fp16 h0 in smem)
            auto phase_sm = [&](uint32_t w_base4, float (*accN)[4]) {
                uint32_t iw[3];
                #pragma unroll
                for (int g = 0; g < 3; ++g)
                    iw[g] = w_base4 + (uint32_t)((g * 16 + wpair) * 16) * 32 + lane;
                for (int j = 0; j < 16; ++j) {
                    int base = (wm * 16 + gID) * H0ST + tig + 8 * j;
                    uint32_t af[4];
                    af[0] = h0s[base];
                    af[1] = h0s[base + 8 * H0ST];
                    af[2] = h0s[base + 4];
                    af[3] = h0s[base + 8 * H0ST + 4];
                    uint4 wv[3];
                    #pragma unroll
                    for (int g = 0; g < 3; ++g)
                        wv[g] = ldg_cg4(&S4[iw[g] + j * 32]);
                    mmastep(af, wv, accN);
                }
            };

            if (layer == 0) {
                phase_pk(XPK4,  W0X4, 8,  aI);   // x part (K=128)
                phase_pk(H0PK4, W0H4, 16, aH);   // h part (K=256)
            } else {
                phase_sm(W1X4, aI);               // h0 (smem fp16) part
                phase_pk(H1PK4, W1H4, 16, aH);   // h part (K=256)
            }

            // ---- elementwise GRU gates ----
            #pragma unroll
            for (int s = 0; s < 2; ++s) {
                const int c = q * 64 + wn * 16 + s * 8 + tig * 2;
                float2 bi0 = *(const float2*)&bih[c];
                float2 bh0 = *(const float2*)&bhh[c];
                float2 bi1 = *(const float2*)&bih[256 + c];
                float2 bh1 = *(const float2*)&bhh[256 + c];
                float2 bIv = *(const float2*)&bih[512 + c];
                float2 bHv = *(const float2*)&bhh[512 + c];
                float2 bRv = make_float2(bi0.x + bh0.x, bi0.y + bh0.y);
                float2 bZv = make_float2(bi1.x + bh1.x, bi1.y + bh1.y);
                const int ra = wm * 16 + gID;
                const int rb = ra + 8;
                float2 ha = *(const float2*)&asrch[(size_t)ra * HDIM + c];
                float2 hb = *(const float2*)&asrch[(size_t)rb * HDIM + c];
                float2 oa, ob;
                oa.x = gru1(aR[s][0] + bRv.x, aZ[s][0] + bZv.x,
                            aI[s][0] + bIv.x, aH[s][0] + bHv.x, ha.x);
                oa.y = gru1(aR[s][1] + bRv.y, aZ[s][1] + bZv.y,
                            aI[s][1] + bIv.y, aH[s][1] + bHv.y, ha.y);
                ob.x = gru1(aR[s][2] + bRv.x, aZ[s][2] + bZv.x,
                            aI[s][2] + bIv.x, aH[s][2] + bHv.x, hb.x);
                ob.y = gru1(aR[s][3] + bRv.y, aZ[s][3] + bZv.y,
                            aI[s][3] + bIv.y, aH[s][3] + bHv.y, hb.y);
                *(float2*)&hdst[(size_t)ra * HDIM + c] = oa;
                *(float2*)&hdst[(size_t)rb * HDIM + c] = ob;
                if (layer == 0) {
                    h0s[ra * H0ST + (c >> 1)] = h2p(oa.x, oa.y);
                    h0s[rb * H0ST + (c >> 1)] = h2p(ob.x, ob.y);
                }
            }
        }
        __syncthreads();   // h0s + hdst complete before layer 1 / heads
    }

    // heads: logits = h1 @ w_p^T + b_p ; value = h1 @ w_v^T + b_v
    {
        const int row = tid >> 3;              // 0..31
        const int qq  = tid & 7;               // 4 logits per thread
        const float* h1r = hbase + (size_t)BATCH * HDIM
                                 + (size_t)(rowbase + row) * HDIM;
        float acc[4];
        #pragma unroll
        for (int a = 0; a < 4; ++a) acc[a] = bp[qq * 4 + a];
        float av = bv[0];
        const float4* h4 = (const float4*)h1r;
        for (int kb = 0; kb < HDIM / 4; ++kb) {
            float4 hv = h4[kb];
            #pragma unroll
            for (int a = 0; a < 4; ++a) {
                const float4 wq =
                    *(const float4*)&wp[(qq * 4 + a) * HDIM + kb * 4];
                acc[a] += hv.x * wq.x + hv.y * wq.y + hv.z * wq.z + hv.w * wq.w;
            }
            if (qq == 0) {
                const float4 wq = *(const float4*)&wv[kb * 4];
                av += hv.x * wq.x + hv.y * wq.y + hv.z * wq.z + hv.w * wq.w;
            }
        }
        #pragma unroll
        for (int a = 0; a < 4; ++a)
            outL[(size_t)(rowbase + row) * ADIM + qq * 4 + a] = acc[a];
        if (qq == 0) outV[rowbase + row] = av;
    }
}

extern "C" void kernel_launch(void* const* d_in, const int* in_sizes, int n_in,
                              void* d_out, int out_size) {
    const float* x    = (const float*)d_in[0];
    const float* hin  = (const float*)d_in[1];
    const float* wih0 = (const float*)d_in[2];
    const float* whh0 = (const float*)d_in[3];
    const float* bih0 = (const float*)d_in[4];
    const float* bhh0 = (const float*)d_in[5];
    const float* wih1 = (const float*)d_in[6];
    const float* whh1 = (const float*)d_in[7];
    const float* bih1 = (const float*)d_in[8];
    const float* bhh1 = (const float*)d_in[9];
    const float* wp   = (const float*)d_in[10];
    const float* bp   = (const float*)d_in[11];
    const float* wv   = (const float*)d_in[12];
    const float* bv   = (const float*)d_in[13];
    float* out = (float*)d_out;

    pack_all<<<1104, 256>>>(x, hin, wih0, whh0, wih1, whh1);

    cudaFuncSetAttribute(gru_ac_kernel,
                         cudaFuncAttributeMaxDynamicSharedMemorySize, SMEM_H0);
    gru_ac_kernel<<<NBLK, NT, SMEM_H0>>>(x, hin, bih0, bhh0, bih1, bhh1,
                                         wp, bp, wv, bv, out);
}

// round 16
// speedup vs baseline: 1.4319x; 1.4319x over previous
#include <cuda_runtime.h>
#include <cuda_fp16.h>
#include <cstdint>

#define BATCH 32768
#define IDIM  128
#define HDIM  256
#define ADIM  32
#define MT    64
#define NT    256
#define NBLK  (BATCH/MT)

// ---- packed fp16 scratch (uint32 units) ----
#define XPK   0u
#define H0PK  2097152u
#define H1PK  6291456u
#define W0X   10485760u
#define W0H   10534912u
#define W1X   10633216u
#define W1H   10731520u
#define SCR_TOTAL 10829824u
__device__ uint32_t scr[SCR_TOTAL];

#define XPK4  (XPK/4)
#define H0PK4 (H0PK/4)
#define H1PK4 (H1PK/4)
#define W0X4  (W0X/4)
#define W0H4  (W0H/4)
#define W1X4  (W1X/4)
#define W1H4  (W1H/4)

static __device__ __forceinline__ uint32_t h2p(float a, float b) {
    __half2 h = __floats2half2_rn(a, b);
    return *reinterpret_cast<uint32_t*>(&h);
}
static __device__ __forceinline__ uint32_t smem_b32(const void* p) {
    uint32_t a;
    asm("{ .reg .u64 t; cvta.to.shared.u64 t, %1; cvt.u32.u64 %0, t; }"
        : "=r"(a) : "l"(p));
    return a;
}
static __device__ __forceinline__ uint4 lds128(uint32_t a) {
    uint4 v;
    asm volatile("ld.shared.v4.u32 {%0,%1,%2,%3}, [%4];"
        : "=r"(v.x), "=r"(v.y), "=r"(v.z), "=r"(v.w) : "r"(a));
    return v;
}
#define CP16(dst, src) \
    asm volatile("cp.async.cg.shared.global [%0], [%1], 16;" \
                 :: "r"(dst), "l"(src) : "memory")
#define CPC()  asm volatile("cp.async.commit_group;" ::: "memory")
#define CPW1() asm volatile("cp.async.wait_group 1;" ::: "memory")
#define CPW0() asm volatile("cp.async.wait_group 0;" ::: "memory")

static __device__ __forceinline__ void mma16(float c[4], const uint32_t a[4],
                                             const uint32_t b[2]) {
    asm volatile(
        "mma.sync.aligned.m16n8k16.row.col.f32.f16.f16.f32 "
        "{%0,%1,%2,%3},{%4,%5,%6,%7},{%8,%9},{%0,%1,%2,%3};"
        : "+f"(c[0]), "+f"(c[1]), "+f"(c[2]), "+f"(c[3])
        : "r"(a[0]), "r"(a[1]), "r"(a[2]), "r"(a[3]), "r"(b[0]), "r"(b[1]));
}
static __device__ __forceinline__ float sigf(float x) {
    return __fdividef(1.0f, 1.0f + __expf(-x));
}
static __device__ __forceinline__ float tanhff(float x) {
    float ax = fabsf(x), e = __expf(-2.0f * ax);
    return copysignf(__fdividef(1.0f - e, 1.0f + e), x);
}
static __device__ __forceinline__ float gru1(float rp, float zp, float ip,
                                             float hp, float hv) {
    float r = sigf(rp), z = sigf(zp);
    float n = tanhff(ip + r * hp);
    return n + z * (hv - n);
}

// ---------- merged pre-kernel: pack weights + A-sources ----------
__global__ void __launch_bounds__(256)
pack_all(const float* __restrict__ x,    const float* __restrict__ hin,
         const float* __restrict__ wih0, const float* __restrict__ whh0,
         const float* __restrict__ wih1, const float* __restrict__ whh1)
{
    int tid = threadIdx.x;
    if (blockIdx.x < 336) {
        int i = blockIdx.x * 256 + tid;
        if (i >= 86016) return;
        const float* src; uint32_t base4; int K; int l = i;
        if (l < 12288)                 { src = wih0; base4 = W0X4; K = 128; }
        else if ((l -= 12288) < 24576) { src = whh0; base4 = W0H4; K = 256; }
        else if ((l -= 24576) < 24576) { src = wih1; base4 = W1X4; K = 256; }
        else { l -= 24576;               src = whh1; base4 = W1H4; K = 256; }
        const int KB = K >> 4;
        int lane = l & 31, blk = l >> 5;
        int j = blk % KB, pair = (blk / KB) & 15, g = blk / (KB * 16);
        int gid = lane >> 2, tig = lane & 3;
        int n_e = g * 256 + pair * 16 + gid;
        int k0  = 16 * j + 2 * tig;
        const float* pe = src + (size_t)n_e * K + k0;
        const float* po = src + (size_t)(n_e + 8) * K + k0;
        uint4 v;
        v.x = h2p(pe[0], pe[1]); v.y = h2p(pe[8], pe[9]);
        v.z = h2p(po[0], po[1]); v.w = h2p(po[8], po[9]);
        ((uint4*)(scr + 0))[base4 + (uint32_t)l] = v;
    } else {
        int bb2 = blockIdx.x - 336;
        int bb = bb2 & 255, m = bb2 >> 8;
        const float* src; uint32_t base4; int K;
        if (m == 0)      { src = x;   base4 = XPK4;  K = IDIM; }
        else if (m == 1) { src = hin; base4 = H0PK4; K = HDIM; }
        else             { src = hin + (size_t)BATCH * HDIM; base4 = H1PK4; K = HDIM; }
        src += (size_t)bb * 128 * K;
        const int KB = K >> 4;
        const int nout = 8 * KB * 32;
        uint4* outp = (uint4*)(scr + 0) + base4 + (size_t)bb * nout;
        for (int o = tid; o < nout; o += 256) {
            int lane = o & 31, j = (o >> 5) % KB, mb = (o >> 5) / KB;
            int gid = lane >> 2, tig = lane & 3;
            int r0 = mb * 16 + gid, k0 = 16 * j + 2 * tig;
            const float* p0 = src + (size_t)r0 * K + k0;
            const float* p1 = src + (size_t)(r0 + 8) * K + k0;
            uint4 v;
            v.x = h2p(p0[0], p0[1]); v.y = h2p(p1[0], p1[1]);
            v.z = h2p(p0[8], p0[9]); v.w = h2p(p1[8], p1[9]);
            outp[o] = v;
        }
    }
}

#define H0ST 132                      // u32 stride per row (256 fp16 + pad)
#define WS_OFF (MT * H0ST)            // u32 offset of W staging = 8448
#define WS_PER_WARP 768               // u32: 2 stages x 3 gates x 128
#define SMEM_TOTAL ((WS_OFF + 8 * WS_PER_WARP) * 4)   // 58368 B

__global__ void __launch_bounds__(NT, 2)
gru_ac_kernel(const float* __restrict__ x,    const float* __restrict__ hin,
              const float* __restrict__ bih0, const float* __restrict__ bhh0,
              const float* __restrict__ bih1, const float* __restrict__ bhh1,
              const float* __restrict__ wp,   const float* __restrict__ bp,
              const float* __restrict__ wv,   const float* __restrict__ bv,
              float* __restrict__ out)
{
    extern __shared__ uint32_t smu[];           // h0s | per-warp W stages
    uint32_t* h0s = smu;
    const uint4* S4 = (const uint4*)(scr + 0);
    const int tid  = threadIdx.x;
    const int lane = tid & 31;
    const int wid  = tid >> 5;
    const int wm   = wid >> 2;     // 0..1 : 32-row band
    const int wn   = wid & 3;      // 0..3 : 16-col band
    const int gID  = lane >> 2;
    const int tig  = lane & 3;
    const int bb   = blockIdx.x;
    const int rowbase = bb * MT;
    // per-warp private W staging (byte address)
    const uint32_t wsb = smem_b32(smu) + (WS_OFF + wid * WS_PER_WARP) * 4
                       + lane * 16;

    float* outL  = out;
    float* outV  = out + (size_t)BATCH * ADIM;
    float* hbase = out + (size_t)BATCH * (ADIM + 1);   // [2][B][H]

    for (int layer = 0; layer < 2; ++layer) {
        const float* bih = layer ? bih1 : bih0;
        const float* bhh = layer ? bhh1 : bhh0;
        const float* asrch = hin + (size_t)layer * BATCH * HDIM
                                 + (size_t)rowbase * HDIM;
        float* hdst = hbase + (size_t)layer * BATCH * HDIM
                            + (size_t)rowbase * HDIM;

        for (int q = 0; q < 4; ++q) {
            float aR[2][2][4], aZ[2][2][4], aI[2][2][4], aH[2][2][4];
            #pragma unroll
            for (int t = 0; t < 2; ++t)
                #pragma unroll
                for (int s = 0; s < 2; ++s)
                    #pragma unroll
                    for (int k = 0; k < 4; ++k) {
                        aR[t][s][k] = 0.f; aZ[t][s][k] = 0.f;
                        aI[t][s][k] = 0.f; aH[t][s][k] = 0.f;
                    }
            const int wpair = q * 4 + wn;

            auto mmastep = [&](const uint32_t af[2][4], const uint4 wv[3],
                               float (*accN)[2][4]) {
                #pragma unroll
                for (int s = 0; s < 2; ++s) {
                    uint32_t bR[2], bZ[2], bN[2];
                    bR[0] = s ? wv[0].z : wv[0].x;
                    bR[1] = s ? wv[0].w : wv[0].y;
                    bZ[0] = s ? wv[1].z : wv[1].x;
                    bZ[1] = s ? wv[1].w : wv[1].y;
                    bN[0] = s ? wv[2].z : wv[2].x;
                    bN[1] = s ? wv[2].w : wv[2].y;
                    #pragma unroll
                    for (int t = 0; t < 2; ++t) {
                        mma16(aR[t][s], af[t], bR);
                        mma16(aZ[t][s], af[t], bZ);
                        mma16(accN[t][s], af[t], bN);
                    }
                }
            };

            // issue W stage for k-index j into buffer slot (j&1)
            auto issueW = [&](const uint32_t iw[3], int j) {
                uint32_t d = wsb + (j & 1) * 1536;
                #pragma unroll
                for (int g = 0; g < 3; ++g)
                    CP16(d + g * 512, S4 + iw[g] + j * 32);
            };
            auto loadW = [&](uint4 wv[3], int j) {
                uint32_t d = wsb + (j & 1) * 1536;
                #pragma unroll
                for (int g = 0; g < 3; ++g)
                    wv[g] = lds128(d + g * 512);
            };

            auto phase_pk = [&](uint32_t a_base4, uint32_t w_base4, int KB,
                                float (*accN)[2][4]) {
                uint32_t ia0 = a_base4
                    + (uint32_t)((bb * 4 + wm * 2) * KB) * 32 + lane;
                uint32_t ia1 = ia0 + (uint32_t)KB * 32;
                uint32_t iw[3];
                #pragma unroll
                for (int g = 0; g < 3; ++g)
                    iw[g] = w_base4 + (uint32_t)((g * 16 + wpair) * KB) * 32 + lane;
                issueW(iw, 0); CPC();
                issueW(iw, 1); CPC();
                for (int j = 0; j < KB; ++j) {
                    CPW1();                       // stage j ready
                    uint4 a0 = S4[ia0 + j * 32];  // A: default (L1) path
                    uint4 a1 = S4[ia1 + j * 32];
                    uint4 wv[3];
                    loadW(wv, j);
                    if (j + 2 < KB) issueW(iw, j + 2);
                    CPC();
                    uint32_t af[2][4] = {{a0.x, a0.y, a0.z, a0.w},
                                         {a1.x, a1.y, a1.z, a1.w}};
                    mmastep(af, wv, accN);
                }
                CPW0();                           // drain trailing groups
            };

            // smem-A phase (layer 1 x-part: A = fp16 h0 in smem)
            auto phase_sm = [&](uint32_t w_base4, float (*accN)[2][4]) {
                uint32_t iw[3];
                #pragma unroll
                for (int g = 0; g < 3; ++g)
                    iw[g] = w_base4 + (uint32_t)((g * 16 + wpair) * 16) * 32 + lane;
                issueW(iw, 0); CPC();
                issueW(iw, 1); CPC();
                for (int j = 0; j < 16; ++j) {
                    CPW1();
                    uint32_t af[2][4];
                    #pragma unroll
                    for (int t = 0; t < 2; ++t) {
                        int base = (wm * 32 + t * 16 + gID) * H0ST + tig + 8 * j;
                        af[t][0] = h0s[base];
                        af[t][1] = h0s[base + 8 * H0ST];
                        af[t][2] = h0s[base + 4];
                        af[t][3] = h0s[base + 8 * H0ST + 4];
                    }
                    uint4 wv[3];
                    loadW(wv, j);
                    if (j + 2 < 16) issueW(iw, j + 2);
                    CPC();
                    mmastep(af, wv, accN);
                }
                CPW0();
            };

            if (layer == 0) {
                phase_pk(XPK4,  W0X4, 8,  aI);   // x part (K=128)
                phase_pk(H0PK4, W0H4, 16, aH);   // h part (K=256)
            } else {
                phase_sm(W1X4, aI);               // h0 (smem fp16) part
                phase_pk(H1PK4, W1H4, 16, aH);   // h part (K=256)
            }

            // ---- elementwise GRU gates ----
            #pragma unroll
            for (int s = 0; s < 2; ++s) {
                const int c = q * 64 + wn * 16 + s * 8 + tig * 2;
                float2 bi0 = *(const float2*)&bih[c];
                float2 bh0 = *(const float2*)&bhh[c];
                float2 bi1 = *(const float2*)&bih[256 + c];
                float2 bh1 = *(const float2*)&bhh[256 + c];
                float2 bIv = *(const float2*)&bih[512 + c];
                float2 bHv = *(const float2*)&bhh[512 + c];
                float2 bRv = make_float2(bi0.x + bh0.x, bi0.y + bh0.y);
                float2 bZv = make_float2(bi1.x + bh1.x, bi1.y + bh1.y);
                #pragma unroll
                for (int t = 0; t < 2; ++t) {
                    const int ra = wm * 32 + t * 16 + gID;
                    const int rb = ra + 8;
                    float2 ha = *(const float2*)&asrch[(size_t)ra * HDIM + c];
                    float2 hb = *(const float2*)&asrch[(size_t)rb * HDIM + c];
                    float2 oa, ob;
                    oa.x = gru1(aR[t][s][0] + bRv.x, aZ[t][s][0] + bZv.x,
                                aI[t][s][0] + bIv.x, aH[t][s][0] + bHv.x, ha.x);
                    oa.y = gru1(aR[t][s][1] + bRv.y, aZ[t][s][1] + bZv.y,
                                aI[t][s][1] + bIv.y, aH[t][s][1] + bHv.y, ha.y);
                    ob.x = gru1(aR[t][s][2] + bRv.x, aZ[t][s][2] + bZv.x,
                                aI[t][s][2] + bIv.x, aH[t][s][2] + bHv.x, hb.x);
                    ob.y = gru1(aR[t][s][3] + bRv.y, aZ[t][s][3] + bZv.y,
                                aI[t][s][3] + bIv.y, aH[t][s][3] + bHv.y, hb.y);
                    *(float2*)&hdst[(size_t)ra * HDIM + c] = oa;
                    *(float2*)&hdst[(size_t)rb * HDIM + c] = ob;
                    if (layer == 0) {
                        h0s[ra * H0ST + (c >> 1)] = h2p(oa.x, oa.y);
                        h0s[rb * H0ST + (c >> 1)] = h2p(ob.x, ob.y);
                    }
                }
            }
        }
        __syncthreads();   // h0s + hdst complete before layer 1 / heads
    }

    // heads: logits = h1 @ w_p^T + b_p ; value = h1 @ w_v^T + b_v
    {
        const int row = tid >> 2;              // 0..63
        const int qq  = tid & 3;
        const float* h1r = hbase + (size_t)BATCH * HDIM
                                 + (size_t)(rowbase + row) * HDIM;
        float acc[8];
        #pragma unroll
        for (int a = 0; a < 8; ++a) acc[a] = bp[qq * 8 + a];
        float av = bv[0];
        const float4* h4 = (const float4*)h1r;
        for (int kb = 0; kb < HDIM / 4; ++kb) {
            float4 hv = h4[kb];
            #pragma unroll
            for (int a = 0; a < 8; ++a) {
                const float4 wq =
                    *(const float4*)&wp[(qq * 8 + a) * HDIM + kb * 4];
                acc[a] += hv.x * wq.x + hv.y * wq.y + hv.z * wq.z + hv.w * wq.w;
            }
            if (qq == 0) {
                const float4 wq = *(const float4*)&wv[kb * 4];
                av += hv.x * wq.x + hv.y * wq.y + hv.z * wq.z + hv.w * wq.w;
            }
        }
        #pragma unroll
        for (int a = 0; a < 8; ++a)
            outL[(size_t)(rowbase + row) * ADIM + qq * 8 + a] = acc[a];
        if (qq == 0) outV[rowbase + row] = av;
    }
}

extern "C" void kernel_launch(void* const* d_in, const int* in_sizes, int n_in,
                              void* d_out, int out_size) {
    const float* x    = (const float*)d_in[0];
    const float* hin  = (const float*)d_in[1];
    const float* wih0 = (const float*)d_in[2];
    const float* whh0 = (const float*)d_in[3];
    const float* bih0 = (const float*)d_in[4];
    const float* bhh0 = (const float*)d_in[5];
    const float* wih1 = (const float*)d_in[6];
    const float* whh1 = (const float*)d_in[7];
    const float* bih1 = (const float*)d_in[8];
    const float* bhh1 = (const float*)d_in[9];
    const float* wp   = (const float*)d_in[10];
    const float* bp   = (const float*)d_in[11];
    const float* wv   = (const float*)d_in[12];
    const float* bv   = (const float*)d_in[13];
    float* out = (float*)d_out;

    pack_all<<<1104, 256>>>(x, hin, wih0, whh0, wih1, whh1);

    cudaFuncSetAttribute(gru_ac_kernel,
                         cudaFuncAttributeMaxDynamicSharedMemorySize, SMEM_TOTAL);
    gru_ac_kernel<<<NBLK, NT, SMEM_TOTAL>>>(x, hin, bih0, bhh0, bih1, bhh1,
                                            wp, bp, wv, bv, out);
}

// round 17
// speedup vs baseline: 1.4996x; 1.0473x over previous
#include <cuda_runtime.h>
#include <cuda_fp16.h>
#include <cstdint>

#define BATCH 32768
#define IDIM  128
#define HDIM  256
#define ADIM  32
#define MT    64
#define NT    256
#define NBLK  (BATCH/MT)

// ---- packed fp16 scratch (uint32 units) ----
#define XPK   0u
#define H0PK  2097152u
#define H1PK  6291456u
#define W0X   10485760u
#define W0H   10534912u
#define W1X   10633216u
#define W1H   10731520u
#define SCR_TOTAL 10829824u
__device__ uint32_t scr[SCR_TOTAL];

#define XPK4  (XPK/4)
#define H0PK4 (H0PK/4)
#define H1PK4 (H1PK/4)
#define W0X4  (W0X/4)
#define W0H4  (W0H/4)
#define W1X4  (W1X/4)
#define W1H4  (W1H/4)

static __device__ __forceinline__ uint32_t h2p(float a, float b) {
    __half2 h = __floats2half2_rn(a, b);
    return *reinterpret_cast<uint32_t*>(&h);
}
static __device__ __forceinline__ uint32_t smem_b32(const void* p) {
    uint32_t a;
    asm("{ .reg .u64 t; cvta.to.shared.u64 t, %1; cvt.u32.u64 %0, t; }"
        : "=r"(a) : "l"(p));
    return a;
}
static __device__ __forceinline__ uint4 lds128(uint32_t a) {
    uint4 v;
    asm volatile("ld.shared.v4.u32 {%0,%1,%2,%3}, [%4];"
        : "=r"(v.x), "=r"(v.y), "=r"(v.z), "=r"(v.w) : "r"(a));
    return v;
}
#define CP16(dst, src) \
    asm volatile("cp.async.cg.shared.global [%0], [%1], 16;" \
                 :: "r"(dst), "l"(src) : "memory")
#define CPC()  asm volatile("cp.async.commit_group;" ::: "memory")
#define CPW3() asm volatile("cp.async.wait_group 3;" ::: "memory")
#define CPW0() asm volatile("cp.async.wait_group 0;" ::: "memory")

static __device__ __forceinline__ void mma16(float c[4], const uint32_t a[4],
                                             const uint32_t b[2]) {
    asm volatile(
        "mma.sync.aligned.m16n8k16.row.col.f32.f16.f16.f32 "
        "{%0,%1,%2,%3},{%4,%5,%6,%7},{%8,%9},{%0,%1,%2,%3};"
        : "+f"(c[0]), "+f"(c[1]), "+f"(c[2]), "+f"(c[3])
        : "r"(a[0]), "r"(a[1]), "r"(a[2]), "r"(a[3]), "r"(b[0]), "r"(b[1]));
}
static __device__ __forceinline__ float sigf(float x) {
    return __fdividef(1.0f, 1.0f + __expf(-x));
}
static __device__ __forceinline__ float tanhff(float x) {
    float ax = fabsf(x), e = __expf(-2.0f * ax);
    return copysignf(__fdividef(1.0f - e, 1.0f + e), x);
}
static __device__ __forceinline__ float gru1(float rp, float zp, float ip,
                                             float hp, float hv) {
    float r = sigf(rp), z = sigf(zp);
    float n = tanhff(ip + r * hp);
    return n + z * (hv - n);
}

// ---------- merged pre-kernel: pack weights + A-sources ----------
__global__ void __launch_bounds__(256)
pack_all(const float* __restrict__ x,    const float* __restrict__ hin,
         const float* __restrict__ wih0, const float* __restrict__ whh0,
         const float* __restrict__ wih1, const float* __restrict__ whh1)
{
    int tid = threadIdx.x;
    if (blockIdx.x < 336) {
        int i = blockIdx.x * 256 + tid;
        if (i >= 86016) return;
        const float* src; uint32_t base4; int K; int l = i;
        if (l < 12288)                 { src = wih0; base4 = W0X4; K = 128; }
        else if ((l -= 12288) < 24576) { src = whh0; base4 = W0H4; K = 256; }
        else if ((l -= 24576) < 24576) { src = wih1; base4 = W1X4; K = 256; }
        else { l -= 24576;               src = whh1; base4 = W1H4; K = 256; }
        const int KB = K >> 4;
        int lane = l & 31, blk = l >> 5;
        int j = blk % KB, pair = (blk / KB) & 15, g = blk / (KB * 16);
        int gid = lane >> 2, tig = lane & 3;
        int n_e = g * 256 + pair * 16 + gid;
        int k0  = 16 * j + 2 * tig;
        const float* pe = src + (size_t)n_e * K + k0;
        const float* po = src + (size_t)(n_e + 8) * K + k0;
        uint4 v;
        v.x = h2p(pe[0], pe[1]); v.y = h2p(pe[8], pe[9]);
        v.z = h2p(po[0], po[1]); v.w = h2p(po[8], po[9]);
        ((uint4*)(scr + 0))[base4 + (uint32_t)l] = v;
    } else {
        int bb2 = blockIdx.x - 336;
        int bb = bb2 & 255, m = bb2 >> 8;
        const float* src; uint32_t base4; int K;
        if (m == 0)      { src = x;   base4 = XPK4;  K = IDIM; }
        else if (m == 1) { src = hin; base4 = H0PK4; K = HDIM; }
        else             { src = hin + (size_t)BATCH * HDIM; base4 = H1PK4; K = HDIM; }
        src += (size_t)bb * 128 * K;
        const int KB = K >> 4;
        const int nout = 8 * KB * 32;
        uint4* outp = (uint4*)(scr + 0) + base4 + (size_t)bb * nout;
        for (int o = tid; o < nout; o += 256) {
            int lane = o & 31, j = (o >> 5) % KB, mb = (o >> 5) / KB;
            int gid = lane >> 2, tig = lane & 3;
            int r0 = mb * 16 + gid, k0 = 16 * j + 2 * tig;
            const float* p0 = src + (size_t)r0 * K + k0;
            const float* p1 = src + (size_t)(r0 + 8) * K + k0;
            uint4 v;
            v.x = h2p(p0[0], p0[1]); v.y = h2p(p1[0], p1[1]);
            v.z = h2p(p0[8], p0[9]); v.w = h2p(p1[8], p1[9]);
            outp[o] = v;
        }
    }
}

#define H0ST 132                      // u32 stride per row (256 fp16 + pad)
#define WS_OFF (MT * H0ST)            // u32 offset of W staging = 8448
#define WS_PER_WARP 1536              // u32: 4 stages x 3 gates x 128
#define SMEM_TOTAL ((WS_OFF + 8 * WS_PER_WARP) * 4)   // 82944 B

__global__ void __launch_bounds__(NT, 2)
gru_ac_kernel(const float* __restrict__ x,    const float* __restrict__ hin,
              const float* __restrict__ bih0, const float* __restrict__ bhh0,
              const float* __restrict__ bih1, const float* __restrict__ bhh1,
              const float* __restrict__ wp,   const float* __restrict__ bp,
              const float* __restrict__ wv,   const float* __restrict__ bv,
              float* __restrict__ out)
{
    extern __shared__ uint32_t smu[];           // h0s | per-warp W stages
    uint32_t* h0s = smu;
    const uint4* S4 = (const uint4*)(scr + 0);
    const int tid  = threadIdx.x;
    const int lane = tid & 31;
    const int wid  = tid >> 5;
    const int wm   = wid >> 2;     // 0..1 : 32-row band
    const int wn   = wid & 3;      // 0..3 : 16-col band
    const int gID  = lane >> 2;
    const int tig  = lane & 3;
    const int bb   = blockIdx.x;
    const int rowbase = bb * MT;
    const uint32_t wsb = smem_b32(smu) + (WS_OFF + wid * WS_PER_WARP) * 4
                       + lane * 16;

    float* outL  = out;
    float* outV  = out + (size_t)BATCH * ADIM;
    float* hbase = out + (size_t)BATCH * (ADIM + 1);   // [2][B][H]

    for (int layer = 0; layer < 2; ++layer) {
        const float* bih = layer ? bih1 : bih0;
        const float* bhh = layer ? bhh1 : bhh0;
        const float* asrch = hin + (size_t)layer * BATCH * HDIM
                                 + (size_t)rowbase * HDIM;
        float* hdst = hbase + (size_t)layer * BATCH * HDIM
                            + (size_t)rowbase * HDIM;

        for (int q = 0; q < 4; ++q) {
            float aR[2][2][4], aZ[2][2][4], aI[2][2][4], aH[2][2][4];
            #pragma unroll
            for (int t = 0; t < 2; ++t)
                #pragma unroll
                for (int s = 0; s < 2; ++s)
                    #pragma unroll
                    for (int k = 0; k < 4; ++k) {
                        aR[t][s][k] = 0.f; aZ[t][s][k] = 0.f;
                        aI[t][s][k] = 0.f; aH[t][s][k] = 0.f;
                    }
            const int wpair = q * 4 + wn;

            auto mmastep = [&](const uint32_t af[2][4], const uint4 wv[3],
                               float (*accN)[2][4]) {
                #pragma unroll
                for (int s = 0; s < 2; ++s) {
                    uint32_t bR[2], bZ[2], bN[2];
                    bR[0] = s ? wv[0].z : wv[0].x;
                    bR[1] = s ? wv[0].w : wv[0].y;
                    bZ[0] = s ? wv[1].z : wv[1].x;
                    bZ[1] = s ? wv[1].w : wv[1].y;
                    bN[0] = s ? wv[2].z : wv[2].x;
                    bN[1] = s ? wv[2].w : wv[2].y;
                    #pragma unroll
                    for (int t = 0; t < 2; ++t) {
                        mma16(aR[t][s], af[t], bR);
                        mma16(aZ[t][s], af[t], bZ);
                        mma16(accN[t][s], af[t], bN);
                    }
                }
            };

            // 4-deep per-warp W staging; slot = j & 3 (1536 B per stage)
            auto issueW = [&](const uint32_t iw[3], int j) {
                uint32_t d = wsb + (j & 3) * 1536;
                #pragma unroll
                for (int g = 0; g < 3; ++g)
                    CP16(d + g * 512, S4 + iw[g] + j * 32);
            };
            auto loadW = [&](uint4 wv[3], int j) {
                uint32_t d = wsb + (j & 3) * 1536;
                #pragma unroll
                for (int g = 0; g < 3; ++g)
                    wv[g] = lds128(d + g * 512);
            };

            auto phase_pk = [&](uint32_t a_base4, uint32_t w_base4, int KB,
                                float (*accN)[2][4]) {
                uint32_t ia0 = a_base4
                    + (uint32_t)((bb * 4 + wm * 2) * KB) * 32 + lane;
                uint32_t ia1 = ia0 + (uint32_t)KB * 32;
                uint32_t iw[3];
                #pragma unroll
                for (int g = 0; g < 3; ++g)
                    iw[g] = w_base4 + (uint32_t)((g * 16 + wpair) * KB) * 32 + lane;
                issueW(iw, 0); CPC();
                issueW(iw, 1); CPC();
                issueW(iw, 2); CPC();
                issueW(iw, 3); CPC();
                for (int j = 0; j < KB; ++j) {
                    CPW3();                       // stage j ready
                    uint4 a0 = S4[ia0 + j * 32];  // A: default (L1) path
                    uint4 a1 = S4[ia1 + j * 32];
                    uint4 wv[3];
                    loadW(wv, j);
                    if (j + 4 < KB) issueW(iw, j + 4);
                    CPC();
                    uint32_t af[2][4] = {{a0.x, a0.y, a0.z, a0.w},
                                         {a1.x, a1.y, a1.z, a1.w}};
                    mmastep(af, wv, accN);
                }
                CPW0();                           // drain trailing groups
            };

            // smem-A phase (layer 1 x-part: A = fp16 h0 in smem)
            auto phase_sm = [&](uint32_t w_base4, float (*accN)[2][4]) {
                uint32_t iw[3];
                #pragma unroll
                for (int g = 0; g < 3; ++g)
                    iw[g] = w_base4 + (uint32_t)((g * 16 + wpair) * 16) * 32 + lane;
                issueW(iw, 0); CPC();
                issueW(iw, 1); CPC();
                issueW(iw, 2); CPC();
                issueW(iw, 3); CPC();
                for (int j = 0; j < 16; ++j) {
                    CPW3();
                    uint32_t af[2][4];
                    #pragma unroll
                    for (int t = 0; t < 2; ++t) {
                        int base = (wm * 32 + t * 16 + gID) * H0ST + tig + 8 * j;
                        af[t][0] = h0s[base];
                        af[t][1] = h0s[base + 8 * H0ST];
                        af[t][2] = h0s[base + 4];
                        af[t][3] = h0s[base + 8 * H0ST + 4];
                    }
                    uint4 wv[3];
                    loadW(wv, j);
                    if (j + 4 < 16) issueW(iw, j + 4);
                    CPC();
                    mmastep(af, wv, accN);
                }
                CPW0();
            };

            if (layer == 0) {
                phase_pk(XPK4,  W0X4, 8,  aI);   // x part (K=128)
                phase_pk(H0PK4, W0H4, 16, aH);   // h part (K=256)
            } else {
                phase_sm(W1X4, aI);               // h0 (smem fp16) part
                phase_pk(H1PK4, W1H4, 16, aH);   // h part (K=256)
            }

            // ---- elementwise GRU gates ----
            #pragma unroll
            for (int s = 0; s < 2; ++s) {
                const int c = q * 64 + wn * 16 + s * 8 + tig * 2;
                float2 bi0 = *(const float2*)&bih[c];
                float2 bh0 = *(const float2*)&bhh[c];
                float2 bi1 = *(const float2*)&bih[256 + c];
                float2 bh1 = *(const float2*)&bhh[256 + c];
                float2 bIv = *(const float2*)&bih[512 + c];
                float2 bHv = *(const float2*)&bhh[512 + c];
                float2 bRv = make_float2(bi0.x + bh0.x, bi0.y + bh0.y);
                float2 bZv = make_float2(bi1.x + bh1.x, bi1.y + bh1.y);
                #pragma unroll
                for (int t = 0; t < 2; ++t) {
                    const int ra = wm * 32 + t * 16 + gID;
                    const int rb = ra + 8;
                    float2 ha = *(const float2*)&asrch[(size_t)ra * HDIM + c];
                    float2 hb = *(const float2*)&asrch[(size_t)rb * HDIM + c];
                    float2 oa, ob;
                    oa.x = gru1(aR[t][s][0] + bRv.x, aZ[t][s][0] + bZv.x,
                                aI[t][s][0] + bIv.x, aH[t][s][0] + bHv.x, ha.x);
                    oa.y = gru1(aR[t][s][1] + bRv.y, aZ[t][s][1] + bZv.y,
                                aI[t][s][1] + bIv.y, aH[t][s][1] + bHv.y, ha.y);
                    ob.x = gru1(aR[t][s][2] + bRv.x, aZ[t][s][2] + bZv.x,
                                aI[t][s][2] + bIv.x, aH[t][s][2] + bHv.x, hb.x);
                    ob.y = gru1(aR[t][s][3] + bRv.y, aZ[t][s][3] + bZv.y,
                                aI[t][s][3] + bIv.y, aH[t][s][3] + bHv.y, hb.y);
                    *(float2*)&hdst[(size_t)ra * HDIM + c] = oa;
                    *(float2*)&hdst[(size_t)rb * HDIM + c] = ob;
                    if (layer == 0) {
                        h0s[ra * H0ST + (c >> 1)] = h2p(oa.x, oa.y);
                        h0s[rb * H0ST + (c >> 1)] = h2p(ob.x, ob.y);
                    }
                }
            }
        }
        __syncthreads();   // h0s + hdst complete before layer 1 / heads
    }

    // heads: logits = h1 @ w_p^T + b_p ; value = h1 @ w_v^T + b_v
    {
        const int row = tid >> 2;              // 0..63
        const int qq  = tid & 3;
        const float* h1r = hbase + (size_t)BATCH * HDIM
                                 + (size_t)(rowbase + row) * HDIM;
        float acc[8];
        #pragma unroll
        for (int a = 0; a < 8; ++a) acc[a] = bp[qq * 8 + a];
        float av = bv[0];
        const float4* h4 = (const float4*)h1r;
        for (int kb = 0; kb < HDIM / 4; ++kb) {
            float4 hv = h4[kb];
            #pragma unroll
            for (int a = 0; a < 8; ++a) {
                const float4 wq =
                    *(const float4*)&wp[(qq * 8 + a) * HDIM + kb * 4];
                acc[a] += hv.x * wq.x + hv.y * wq.y + hv.z * wq.z + hv.w * wq.w;
            }
            if (qq == 0) {
                const float4 wq = *(const float4*)&wv[kb * 4];
                av += hv.x * wq.x + hv.y * wq.y + hv.z * wq.z + hv.w * wq.w;
            }
        }
        #pragma unroll
        for (int a = 0; a < 8; ++a)
            outL[(size_t)(rowbase + row) * ADIM + qq * 8 + a] = acc[a];
        if (qq == 0) outV[rowbase + row] = av;
    }
}

extern "C" void kernel_launch(void* const* d_in, const int* in_sizes, int n_in,
                              void* d_out, int out_size) {
    const float* x    = (const float*)d_in[0];
    const float* hin  = (const float*)d_in[1];
    const float* wih0 = (const float*)d_in[2];
    const float* whh0 = (const float*)d_in[3];
    const float* bih0 = (const float*)d_in[4];
    const float* bhh0 = (const float*)d_in[5];
    const float* bih1 = (const float*)d_in[8];
    const float* bhh1 = (const float*)d_in[9];
    const float* wih1 = (const float*)d_in[6];
    const float* whh1 = (const float*)d_in[7];
    const float* wp   = (const float*)d_in[10];
    const float* bp   = (const float*)d_in[11];
    const float* wv   = (const float*)d_in[12];
    const float* bv   = (const float*)d_in[13];
    float* out = (float*)d_out;

    pack_all<<<1104, 256>>>(x, hin, wih0, whh0, wih1, whh1);

    cudaFuncSetAttribute(gru_ac_kernel,
                         cudaFuncAttributeMaxDynamicSharedMemorySize, SMEM_TOTAL);
    gru_ac_kernel<<<NBLK, NT, SMEM_TOTAL>>>(x, hin, bih0, bhh0, bih1, bhh1,
                                            wp, bp, wv, bv, out);
}